// round 14
// baseline (speedup 1.0000x reference)
#include <cuda_runtime.h>
#include <cuda_fp16.h>
#include <cstdint>

#define LDIM   4800
#define CDIM   256
#define BATCH  2
#define BM     64
#define BN     128
#define BK     64
#define NTM    75          // 4800/64, exact
#define NTN    38          // ceil(4800/128)
#define THRV   0.2f
#define CCOLS  1024
#define CROWS  64
#define TPAD   136         // e2 smem tile row stride in halfs

// ---------------- static device scratch (no allocations) ----------------------
__device__ __half g_h0[BATCH * LDIM * CDIM];
__device__ __half g_h1[BATCH * LDIM * CDIM];
__device__ __half g_e2[(size_t)BATCH * LDIM * LDIM];   // staged e^2, fp16 (92 MB)
__device__ float        g_rowpart[BATCH * LDIM * NTN];
__device__ float        g_colpart[BATCH * NTM * LDIM];
__device__ float        g_invR[BATCH * LDIM];
__device__ float        g_invC[BATCH * LDIM];
__device__ unsigned int g_rowmaxv[BATCH * LDIM];
__device__ unsigned int g_colmaxv[BATCH * LDIM];
__device__ int          g_flag;

// ---------------- helpers ------------------------------------------------------
static __device__ __forceinline__ uint32_t smem_u32(const void* p) {
    uint32_t a;
    asm("{ .reg .u64 t; cvta.to.shared.u64 t, %1; cvt.u32.u64 %0, t; }" : "=r"(a) : "l"(p));
    return a;
}
#define CP16(saddr, gptr) \
    asm volatile("cp.async.cg.shared.global [%0], [%1], 16;" :: "r"(saddr), "l"(gptr) : "memory")
#define CP_COMMIT() asm volatile("cp.async.commit_group;" ::: "memory")
#define CP_WAIT(n)  asm volatile("cp.async.wait_group %0;" :: "n"(n) : "memory")

static __device__ __forceinline__ void ldsm4(uint32_t* f, uint32_t addr) {
    asm volatile("ldmatrix.sync.aligned.m8n8.x4.shared.b16 {%0,%1,%2,%3}, [%4];"
                 : "=r"(f[0]), "=r"(f[1]), "=r"(f[2]), "=r"(f[3]) : "r"(addr));
}
static __device__ __forceinline__ void mma16816(float* d, const uint32_t* a,
                                                uint32_t b0, uint32_t b1) {
    asm volatile("mma.sync.aligned.m16n8k16.row.col.f32.f16.f16.f32 "
                 "{%0,%1,%2,%3}, {%4,%5,%6,%7}, {%8,%9}, {%0,%1,%2,%3};"
                 : "+f"(d[0]), "+f"(d[1]), "+f"(d[2]), "+f"(d[3])
                 : "r"(a[0]), "r"(a[1]), "r"(a[2]), "r"(a[3]), "r"(b0), "r"(b1));
}
// fast exp2: FFMA-only. rel err ~2e-6.
static __device__ __forceinline__ float fexp2(float y) {
    float m = y + 12582912.f;
    float r = y - (m - 12582912.f);
    float p =               1.3333558e-3f;
    p = fmaf(p, r,          9.6181291e-3f);
    p = fmaf(p, r,          5.5504109e-2f);
    p = fmaf(p, r,          2.4022651e-1f);
    p = fmaf(p, r,          6.9314718e-1f);
    p = fmaf(p, r,          1.0f);
    return __uint_as_float(__float_as_uint(p) + (__float_as_uint(m) << 23));
}
__device__ __forceinline__ bool border_ok(int idx) {
    int h = idx / 80, w = idx % 80;
    return (h >= 2) && (h < 58) && (w >= 2) && (w < 78);
}

// smem: 3 stages x (A 8KB + B 16KB) = 72KB. 3 CTAs/SM x 72KB = 216KB <= 228KB.
// Stage st: A @ st*24576, B @ st*24576 + 8192. Epilogue reuses [0, 17408) tile.
#define SMEM_BYTES 73728

// ---------------- Pass 0: fp32 -> fp16 -----------------------------------------
__global__ void k_split(const float* __restrict__ f0, const float* __restrict__ f1) {
    const int NH = BATCH * LDIM * CDIM / 8;
    int t = blockIdx.x * blockDim.x + threadIdx.x;
    if (t >= 2 * NH) return;
    int half = (t >= NH);
    size_t off = (size_t)(half ? t - NH : t) * 8;
    const float4* s = (const float4*)((half ? f1 : f0) + off);
    float4 a = s[0], b = s[1];
    float x[8] = {a.x, a.y, a.z, a.w, b.x, b.y, b.z, b.w};
    uint32_t hw[4];
#pragma unroll
    for (int i = 0; i < 4; i++) {
        __half2 h = __floats2half2_rn(x[2 * i], x[2 * i + 1]);
        hw[i] = *(uint32_t*)&h;
    }
    *(uint4*)((half ? g_h1 : g_h0) + off) = make_uint4(hw[0], hw[1], hw[2], hw[3]);
}

// ---------------- Pass 1: HMMA GEMM 64x128 tile, 3 CTAs/SM ---------------------
__global__ __launch_bounds__(256, 3)
void k_gemm_hmma(const float* __restrict__ tempp, float* __restrict__ mconf)
{
    extern __shared__ char smc[];
    const uint32_t sbase = smem_u32(smc);

    const int b  = blockIdx.z;
    const int mt = blockIdx.y;
    const int nt = blockIdx.x;
    const int l0 = mt * BM;            // M exact: no bounds needed
    const int s0 = nt * BN;
    const int tid  = threadIdx.x;
    const int lane = tid & 31;
    const int wid  = tid >> 5;
    const int wm   = wid & 1;          // 2 warps in M (32 rows each)
    const int wn   = wid >> 1;         // 4 warps in N (32 cols each)
    const size_t bb = (size_t)b * LDIM * CDIM;

    float acc[2][4][4];
#pragma unroll
    for (int i = 0; i < 2; i++)
#pragma unroll
        for (int j = 0; j < 4; j++)
#pragma unroll
            for (int q = 0; q < 4; q++) acc[i][j][q] = 0.f;

    auto issue = [&](int c) {
        const uint32_t st = (uint32_t)(c % 3) * 24576u;
        const __half* A = g_h0 + bb + c * BK;
        const __half* B = g_h1 + bb + c * BK;
#pragma unroll
        for (int i = 0; i < 2; i++) {                     // A: 512 uint4
            int v = tid + 256 * i;
            int r = v >> 3, u = v & 7;
            uint32_t off = (uint32_t)(r * 128 + ((u ^ (r & 7)) << 4));
            CP16(sbase + st + off, (const char*)(A + (size_t)(l0 + r) * CDIM + u * 8));
        }
#pragma unroll
        for (int i = 0; i < 4; i++) {                     // B: 1024 uint4
            int v = tid + 256 * i;
            int r = v >> 3, u = v & 7;
            uint32_t off = (uint32_t)(r * 128 + ((u ^ (r & 7)) << 4));
            int gr = s0 + r; if (gr >= LDIM) gr = 0;
            CP16(sbase + st + 8192 + off, (const char*)(B + (size_t)gr * CDIM + u * 8));
        }
    };

    issue(0); CP_COMMIT();
    issue(1); CP_COMMIT();

    for (int c = 0; c < 4; c++) {
        if (c < 3) CP_WAIT(1); else CP_WAIT(0);
        __syncthreads();

        const uint32_t st = (uint32_t)(c % 3) * 24576u;
#pragma unroll
        for (int ks = 0; ks < 4; ks++) {
            uint32_t af[2][4], bf[2][4];
            const uint32_t cu = (uint32_t)((ks * 2 + (lane >> 4)) << 4);
#pragma unroll
            for (int mb = 0; mb < 2; mb++) {
                int row = wm * 32 + mb * 16 + (lane & 15);
                uint32_t off = (uint32_t)(row * 128) + (cu ^ (uint32_t)((row & 7) << 4));
                ldsm4(af[mb], sbase + st + off);
            }
#pragma unroll
            for (int ng = 0; ng < 2; ng++) {
                int row = wn * 32 + ng * 16 + (lane & 15);
                uint32_t off = (uint32_t)(row * 128) + (cu ^ (uint32_t)((row & 7) << 4));
                ldsm4(bf[ng], sbase + st + 8192 + off);
            }
#pragma unroll
            for (int mb = 0; mb < 2; mb++)
#pragma unroll
                for (int nb = 0; nb < 4; nb++)
                    mma16816(acc[mb][nb], af[mb], bf[nb >> 1][nb & 1], bf[nb >> 1][(nb & 1) + 2]);
        }

        if (c < 2) { issue(c + 2); CP_COMMIT(); }
    }
    __syncthreads();

    // ---- epilogue: e = 2^(sim*scale); fp32 sums; e^2 -> smem tile; mconf 0 ----
    const float scale = tempp[0] * (1.4426950408889634f / 256.0f);
    const int lrow = wm * 32 + (lane >> 2);
    const int lcol = wn * 32 + 2 * (lane & 3);
    __half* tile = (__half*)smc;                      // [64][TPAD] halfs, 17408 B

    float rsum[4] = {0.f, 0.f, 0.f, 0.f};
    float csum0[4], csum1[4];
#pragma unroll
    for (int nb = 0; nb < 4; nb++) { csum0[nb] = 0.f; csum1[nb] = 0.f; }

#pragma unroll
    for (int mb = 0; mb < 2; mb++) {
        const int lrA = lrow + mb * 16;
        const int glA = l0 + lrA;                    // always valid
        const int glB = glA + 8;
#pragma unroll
        for (int nb = 0; nb < 4; nb++) {
            const int lc = lcol + nb * 8;
            const int gc = s0 + lc;
            const bool vc = gc < LDIM;
            float e0 = fexp2(acc[mb][nb][0] * scale);
            float e1 = fexp2(acc[mb][nb][1] * scale);
            float e2 = fexp2(acc[mb][nb][2] * scale);
            float e3 = fexp2(acc[mb][nb][3] * scale);
            if (!vc) { e0 = 0.f; e1 = 0.f; e2 = 0.f; e3 = 0.f; }
            rsum[mb * 2 + 0] += e0 + e1;
            rsum[mb * 2 + 1] += e2 + e3;
            csum0[nb] += e0 + e2;
            csum1[nb] += e1 + e3;
            *(__half2*)(tile + lrA * TPAD + lc)       = __floats2half2_rn(e0 * e0, e1 * e1);
            *(__half2*)(tile + (lrA + 8) * TPAD + lc) = __floats2half2_rn(e2 * e2, e3 * e3);
            if (vc) {
                *(float2*)(mconf + ((size_t)b * LDIM + glA) * LDIM + gc) = make_float2(0.f, 0.f);
                *(float2*)(mconf + ((size_t)b * LDIM + glB) * LDIM + gc) = make_float2(0.f, 0.f);
            }
        }
    }
    __syncthreads();

    // coalesced e2 flush: 64 rows x 128 cols half = 1024 uint4, 4 per thread
#pragma unroll
    for (int i = 0; i < 4; i++) {
        int idx = tid + 256 * i;
        int row = idx >> 4, u = idx & 15;
        int gc = s0 + u * 8;
        if (gc < LDIM) {
            uint4 v = *(uint4*)(tile + row * TPAD + u * 8);
            *(uint4*)(g_e2 + ((size_t)b * LDIM + (l0 + row)) * LDIM + gc) = v;
        }
    }

#pragma unroll
    for (int h = 0; h < 4; h++) {
        rsum[h] += __shfl_xor_sync(0xFFFFFFFFu, rsum[h], 1);
        rsum[h] += __shfl_xor_sync(0xFFFFFFFFu, rsum[h], 2);
    }
#pragma unroll
    for (int nb = 0; nb < 4; nb++) {
#pragma unroll
        for (int o = 4; o <= 16; o <<= 1) {
            csum0[nb] += __shfl_xor_sync(0xFFFFFFFFu, csum0[nb], o);
            csum1[nb] += __shfl_xor_sync(0xFFFFFFFFu, csum1[nb], o);
        }
    }
    __syncthreads();     // tile flushed; reuse smem for rs/cs

    float* rs = (float*)smc;            // [4 wn][64 rows]
    float* cs = (float*)(smc + 1024);   // [2 wm][128 cols]
    if ((lane & 3) == 0) {
#pragma unroll
        for (int h = 0; h < 4; h++) {
            int rl = wm * 32 + (h >> 1) * 16 + (h & 1) * 8 + (lane >> 2);
            rs[wn * 64 + rl] = rsum[h];
        }
    }
    if (lane < 4) {
#pragma unroll
        for (int nb = 0; nb < 4; nb++) {
            int cl = wn * 32 + nb * 8 + 2 * lane;
            cs[wm * 128 + cl]     = csum0[nb];
            cs[wm * 128 + cl + 1] = csum1[nb];
        }
    }
    __syncthreads();
    if (tid < 64) {
        float rv = rs[tid] + rs[64 + tid] + rs[128 + tid] + rs[192 + tid];
        g_rowpart[((size_t)b * LDIM + l0 + tid) * NTN + nt] = rv;
    }
    if (tid < 128) {
        float cv = cs[tid] + cs[128 + tid];
        if (s0 + tid < LDIM)
            g_colpart[((size_t)b * NTM + mt) * LDIM + s0 + tid] = cv;
    }
}

// ---------------- Pass 1b: fixed-order reduce; reset max values ----------------
__global__ void k_reduce()
{
    int t = blockIdx.x * blockDim.x + threadIdx.x;
    const int n = BATCH * LDIM;
    if (t < n) {
        float s = 0.f;
#pragma unroll
        for (int i = 0; i < NTN; i++) s += g_rowpart[(size_t)t * NTN + i];
        g_invR[t]    = 1.f / s;
        g_rowmaxv[t] = 0u;
    } else if (t < 2 * n) {
        int u = t - n;
        int b = u / LDIM, sidx = u % LDIM;
        float s = 0.f;
        for (int i = 0; i < NTM; i++) s += g_colpart[((size_t)b * NTM + i) * LDIM + sidx];
        g_invC[u]    = 1.f / s;
        g_colmaxv[u] = 0u;
    }
}

// ---------------- Pass 2: conf = e2*invR*invC from fp16 scratch ----------------
__global__ __launch_bounds__(256)
void k_conf(float* __restrict__ conf)
{
    const int b  = blockIdx.z;
    const int l0 = blockIdx.y * CROWS;
    const int s0 = blockIdx.x * CCOLS;
    const int t  = threadIdx.x, warp = t >> 5, lane = t & 31;
    const int j0 = s0 + 4 * t;
    const bool jok = j0 < LDIM;

    __shared__ float sInvR[CROWS];
    __shared__ float wr[8][CROWS];

    if (t < CROWS) sInvR[t] = g_invR[b * LDIM + l0 + t];
    __syncthreads();

    const float4 invc = jok ? *(const float4*)(g_invC + b * LDIM + j0)
                            : make_float4(0.f, 0.f, 0.f, 0.f);

    float4 cv = make_float4(0.f, 0.f, 0.f, 0.f);
    size_t base = ((size_t)b * LDIM + l0) * LDIM + (jok ? j0 : 0);

#pragma unroll 2
    for (int r = 0; r < CROWS; r++, base += LDIM) {
        float rm = 0.f;
        if (jok) {
            uint2 raw = *(const uint2*)(g_e2 + base);
            float2 f01 = __half22float2(*(__half2*)&raw.x);
            float2 f23 = __half22float2(*(__half2*)&raw.y);
            const float tR = sInvR[r];
            float4 cf;
            cf.x = f01.x * (tR * invc.x);
            cf.y = f01.y * (tR * invc.y);
            cf.z = f23.x * (tR * invc.z);
            cf.w = f23.y * (tR * invc.w);
            *(float4*)(conf + base) = cf;

            cv.x = fmaxf(cv.x, cf.x);
            cv.y = fmaxf(cv.y, cf.y);
            cv.z = fmaxf(cv.z, cf.z);
            cv.w = fmaxf(cv.w, cf.w);
            rm = fmaxf(fmaxf(cf.x, cf.y), fmaxf(cf.z, cf.w));
        }
#pragma unroll
        for (int o = 16; o > 0; o >>= 1)
            rm = fmaxf(rm, __shfl_xor_sync(0xFFFFFFFFu, rm, o));
        if (lane == 0) wr[warp][r] = rm;
    }

    if (jok) {
        atomicMax(&g_colmaxv[b * LDIM + j0 + 0], __float_as_uint(cv.x));
        atomicMax(&g_colmaxv[b * LDIM + j0 + 1], __float_as_uint(cv.y));
        atomicMax(&g_colmaxv[b * LDIM + j0 + 2], __float_as_uint(cv.z));
        atomicMax(&g_colmaxv[b * LDIM + j0 + 3], __float_as_uint(cv.w));
    }
    __syncthreads();
    if (t < CROWS) {
        float m = wr[0][t];
#pragma unroll
        for (int w = 1; w < 8; w++) m = fmaxf(m, wr[w][t]);
        atomicMax(&g_rowmaxv[b * LDIM + l0 + t], __float_as_uint(m));
    }
}

// ---------------- Pass 2b: flag = any(rowmax > THR) ----------------------------
__global__ void k_flag()
{
    __shared__ int any;
    if (threadIdx.x == 0) any = 0;
    __syncthreads();
    int loc = 0;
    for (int i = threadIdx.x; i < BATCH * LDIM; i += 256)
        if (__uint_as_float(g_rowmaxv[i]) > THRV) loc = 1;
    if (loc) any = 1;
    __syncthreads();
    if (threadIdx.x == 0) g_flag = any;
}

// ---------------- Pass 3: equality-based mutual-NN recovery (early-exit) -------
__global__ __launch_bounds__(256)
void k_recover(const float* __restrict__ conf, float* __restrict__ mconf)
{
    if (g_flag == 0) return;
    const int b  = blockIdx.z;
    const int l0 = blockIdx.y * CROWS;
    const int s0 = blockIdx.x * CCOLS;
    const int t  = threadIdx.x;
    const int j0 = s0 + 4 * t;
    const bool jok = j0 < LDIM;

    __shared__ float srm[CROWS];
    __shared__ int bany;
    if (t == 0) bany = 0;
    __syncthreads();
    if (t < CROWS) {
        float v = __uint_as_float(g_rowmaxv[b * LDIM + l0 + t]);
        srm[t] = v;
        if (v > THRV) bany = 1;
    }
    __syncthreads();
    if (!bany || !jok) return;

    float4 cm;
    cm.x = __uint_as_float(g_colmaxv[b * LDIM + j0 + 0]);
    cm.y = __uint_as_float(g_colmaxv[b * LDIM + j0 + 1]);
    cm.z = __uint_as_float(g_colmaxv[b * LDIM + j0 + 2]);
    cm.w = __uint_as_float(g_colmaxv[b * LDIM + j0 + 3]);
    const bool bj0 = border_ok(j0), bj1 = border_ok(j0 + 1),
               bj2 = border_ok(j0 + 2), bj3 = border_ok(j0 + 3);

    size_t base = ((size_t)b * LDIM + l0) * LDIM + j0;
    for (int r = 0; r < CROWS; r++, base += LDIM) {
        const float rm = srm[r];
        if (rm > THRV && border_ok(l0 + r)) {
            float4 cf = *(const float4*)(conf + base);
            if (cf.x > THRV && cf.x == rm && cf.x == cm.x && bj0) mconf[base + 0] = cf.x;
            if (cf.y > THRV && cf.y == rm && cf.y == cm.y && bj1) mconf[base + 1] = cf.y;
            if (cf.z > THRV && cf.z == rm && cf.z == cm.z && bj2) mconf[base + 2] = cf.z;
            if (cf.w > THRV && cf.w == rm && cf.w == cm.w && bj3) mconf[base + 3] = cf.w;
        }
    }
}

// ---------------- launch -------------------------------------------------------
extern "C" void kernel_launch(void* const* d_in, const int* in_sizes, int n_in,
                              void* d_out, int out_size)
{
    const float *f0 = nullptr, *f1 = nullptr, *temp = nullptr;
    for (int i = 0; i < n_in; i++) {
        if (in_sizes[i] == 1) { if (!temp) temp = (const float*)d_in[i]; }
        else { if (!f0) f0 = (const float*)d_in[i]; else if (!f1) f1 = (const float*)d_in[i]; }
    }

    float* conf  = (float*)d_out;
    float* mconf = conf + (size_t)out_size / 2;

    cudaFuncSetAttribute(k_gemm_hmma, cudaFuncAttributeMaxDynamicSharedMemorySize, SMEM_BYTES);

    const int NSPLIT = 2 * BATCH * LDIM * CDIM / 8;
    k_split<<<(NSPLIT + 255) / 256, 256>>>(f0, f1);

    dim3 g1(NTN, NTM, BATCH);
    k_gemm_hmma<<<g1, 256, SMEM_BYTES>>>(temp, mconf);

    const int n2 = 2 * BATCH * LDIM;
    k_reduce<<<(n2 + 255) / 256, 256>>>();

    dim3 g2((LDIM + CCOLS - 1) / CCOLS, LDIM / CROWS, BATCH);
    k_conf<<<g2, 256>>>(conf);

    k_flag<<<1, 256>>>();
    k_recover<<<g2, 256>>>(conf, mconf);
}

// round 15
// speedup vs baseline: 1.1192x; 1.1192x over previous
#include <cuda_runtime.h>
#include <cuda_fp16.h>
#include <cstdint>

#define LDIM   4800
#define CDIM   256
#define BATCH  2
#define BM     128
#define BN     128
#define BK     64
#define NT     38          // ceil(4800/128)
#define THRV   0.2f
#define CCOLS  1024        // k_conf cols per block (4 per thread)
#define CROWS  32          // k_conf rows per block (grid 1500 -> ~10 CTA/SM)
#define TPAD   136         // e2 smem tile row stride in halfs

// ---------------- static device scratch (no allocations) ----------------------
__device__ __half g_h0[BATCH * LDIM * CDIM];
__device__ __half g_h1[BATCH * LDIM * CDIM];
__device__ __half g_e2[(size_t)BATCH * LDIM * LDIM];   // staged e^2, fp16 (92 MB)
__device__ float        g_rowpart[BATCH * LDIM * NT];
__device__ float        g_colpart[BATCH * NT * LDIM];
__device__ float        g_invR[BATCH * LDIM];
__device__ float        g_invC[BATCH * LDIM];
__device__ unsigned int g_rowmaxv[BATCH * LDIM];
__device__ unsigned int g_colmaxv[BATCH * LDIM];
__device__ int          g_flag;

// ---------------- helpers ------------------------------------------------------
static __device__ __forceinline__ uint32_t smem_u32(const void* p) {
    uint32_t a;
    asm("{ .reg .u64 t; cvta.to.shared.u64 t, %1; cvt.u32.u64 %0, t; }" : "=r"(a) : "l"(p));
    return a;
}
#define CP16(saddr, gptr) \
    asm volatile("cp.async.cg.shared.global [%0], [%1], 16;" :: "r"(saddr), "l"(gptr) : "memory")
#define CP_COMMIT() asm volatile("cp.async.commit_group;" ::: "memory")
#define CP_WAIT(n)  asm volatile("cp.async.wait_group %0;" :: "n"(n) : "memory")

static __device__ __forceinline__ void ldsm4(uint32_t* f, uint32_t addr) {
    asm volatile("ldmatrix.sync.aligned.m8n8.x4.shared.b16 {%0,%1,%2,%3}, [%4];"
                 : "=r"(f[0]), "=r"(f[1]), "=r"(f[2]), "=r"(f[3]) : "r"(addr));
}
static __device__ __forceinline__ void mma16816(float* d, const uint32_t* a,
                                                uint32_t b0, uint32_t b1) {
    asm volatile("mma.sync.aligned.m16n8k16.row.col.f32.f16.f16.f32 "
                 "{%0,%1,%2,%3}, {%4,%5,%6,%7}, {%8,%9}, {%0,%1,%2,%3};"
                 : "+f"(d[0]), "+f"(d[1]), "+f"(d[2]), "+f"(d[3])
                 : "r"(a[0]), "r"(a[1]), "r"(a[2]), "r"(a[3]), "r"(b0), "r"(b1));
}
// fast exp2: FFMA-only. rel err ~2e-6.
static __device__ __forceinline__ float fexp2(float y) {
    float m = y + 12582912.f;
    float r = y - (m - 12582912.f);
    float p =               1.3333558e-3f;
    p = fmaf(p, r,          9.6181291e-3f);
    p = fmaf(p, r,          5.5504109e-2f);
    p = fmaf(p, r,          2.4022651e-1f);
    p = fmaf(p, r,          6.9314718e-1f);
    p = fmaf(p, r,          1.0f);
    return __uint_as_float(__float_as_uint(p) + (__float_as_uint(m) << 23));
}
__device__ __forceinline__ bool border_ok(int idx) {
    int h = idx / 80, w = idx % 80;
    return (h >= 2) && (h < 58) && (w >= 2) && (w < 78);
}

// smem: 3 stages x (A 16KB + B 16KB). 2 CTAs/SM x 96KB = 192KB <= 228KB.
// Epilogue reuses [0, 34816) as the e2 half tile [128][TPAD].
#define SMEM_BYTES 98304

// ---------------- Pass 0: fp32 -> fp16 -----------------------------------------
__global__ void k_split(const float* __restrict__ f0, const float* __restrict__ f1) {
    const int NH = BATCH * LDIM * CDIM / 8;
    int t = blockIdx.x * blockDim.x + threadIdx.x;
    if (t >= 2 * NH) return;
    int half = (t >= NH);
    size_t off = (size_t)(half ? t - NH : t) * 8;
    const float4* s = (const float4*)((half ? f1 : f0) + off);
    float4 a = s[0], b = s[1];
    float x[8] = {a.x, a.y, a.z, a.w, b.x, b.y, b.z, b.w};
    uint32_t hw[4];
#pragma unroll
    for (int i = 0; i < 4; i++) {
        __half2 h = __floats2half2_rn(x[2 * i], x[2 * i + 1]);
        hw[i] = *(uint32_t*)&h;
    }
    *(uint4*)((half ? g_h1 : g_h0) + off) = make_uint4(hw[0], hw[1], hw[2], hw[3]);
}

// ---------------- Pass 1: HMMA GEMM (fp16), coalesced e^2 via smem -------------
__global__ __launch_bounds__(256, 2)
void k_gemm_hmma(const float* __restrict__ tempp, float* __restrict__ mconf)
{
    extern __shared__ char smc[];
    const uint32_t sbase = smem_u32(smc);
    const uint32_t sA[3] = {sbase,         sbase + 16384, sbase + 32768};
    const uint32_t sB[3] = {sbase + 49152, sbase + 65536, sbase + 81920};

    const int b  = blockIdx.z;
    const int mt = blockIdx.y;
    const int nt = blockIdx.x;
    const int l0 = mt * BM;
    const int s0 = nt * BN;
    const int tid  = threadIdx.x;
    const int lane = tid & 31;
    const int wid  = tid >> 5;
    const int wm   = wid & 3;
    const int wn   = wid >> 2;
    const size_t bb = (size_t)b * LDIM * CDIM;

    float acc[2][8][4];
#pragma unroll
    for (int i = 0; i < 2; i++)
#pragma unroll
        for (int j = 0; j < 8; j++)
#pragma unroll
            for (int q = 0; q < 4; q++) acc[i][j][q] = 0.f;

    auto issue = [&](int c) {
        const int st = c % 3;
        const __half* A = g_h0 + bb + c * BK;
        const __half* B = g_h1 + bb + c * BK;
#pragma unroll
        for (int i = 0; i < 4; i++) {
            int v = tid + 256 * i;
            int r = v >> 3, u = v & 7;
            uint32_t off = (uint32_t)(r * 128 + ((u ^ (r & 7)) << 4));
            int ga = l0 + r; if (ga >= LDIM) ga = 0;
            CP16(sA[st] + off, (const char*)(A + (size_t)ga * CDIM + u * 8));
            int gbr = s0 + r; if (gbr >= LDIM) gbr = 0;
            CP16(sB[st] + off, (const char*)(B + (size_t)gbr * CDIM + u * 8));
        }
    };

    issue(0); CP_COMMIT();
    issue(1); CP_COMMIT();

    for (int c = 0; c < 4; c++) {
        if (c < 3) CP_WAIT(1); else CP_WAIT(0);
        __syncthreads();

        const int st = c % 3;
#pragma unroll
        for (int ks = 0; ks < 4; ks++) {
            uint32_t af[2][4], bf[4][4];
            const uint32_t cu = (uint32_t)((ks * 2 + (lane >> 4)) << 4);
#pragma unroll
            for (int mb = 0; mb < 2; mb++) {
                int row = wm * 32 + mb * 16 + (lane & 15);
                uint32_t off = (uint32_t)(row * 128) + (cu ^ (uint32_t)((row & 7) << 4));
                ldsm4(af[mb], sA[st] + off);
            }
#pragma unroll
            for (int ng = 0; ng < 4; ng++) {
                int row = wn * 64 + ng * 16 + (lane & 15);
                uint32_t off = (uint32_t)(row * 128) + (cu ^ (uint32_t)((row & 7) << 4));
                ldsm4(bf[ng], sB[st] + off);
            }
#pragma unroll
            for (int mb = 0; mb < 2; mb++)
#pragma unroll
                for (int nb = 0; nb < 8; nb++)
                    mma16816(acc[mb][nb], af[mb], bf[nb >> 1][nb & 1], bf[nb >> 1][(nb & 1) + 2]);
        }

        if (c < 2) { issue(c + 2); CP_COMMIT(); }
    }
    __syncthreads();

    // ---- epilogue: e = 2^(sim*scale); sums fp32; e^2 -> smem tile; mconf 0 ----
    const float scale = tempp[0] * (1.4426950408889634f / 256.0f);
    const int lrow = wm * 32 + (lane >> 2);
    const int lcol = wn * 64 + 2 * (lane & 3);
    __half* tile = (__half*)smc;                      // [128][TPAD] halfs

    float rsum[4] = {0.f, 0.f, 0.f, 0.f};
    float csum0[8], csum1[8];
#pragma unroll
    for (int nb = 0; nb < 8; nb++) { csum0[nb] = 0.f; csum1[nb] = 0.f; }

#pragma unroll
    for (int mb = 0; mb < 2; mb++) {
        const int lrA = lrow + mb * 16;
        const int glA = l0 + lrA;
        const int glB = glA + 8;
        const bool vA = glA < LDIM, vB = glB < LDIM;
#pragma unroll
        for (int nb = 0; nb < 8; nb++) {
            const int lc = lcol + nb * 8;
            const int gc = s0 + lc;
            const bool vc = gc < LDIM;
            float e0 = fexp2(acc[mb][nb][0] * scale);
            float e1 = fexp2(acc[mb][nb][1] * scale);
            float e2 = fexp2(acc[mb][nb][2] * scale);
            float e3 = fexp2(acc[mb][nb][3] * scale);
            if (!(vA && vc)) { e0 = 0.f; e1 = 0.f; }
            if (!(vB && vc)) { e2 = 0.f; e3 = 0.f; }
            rsum[mb * 2 + 0] += e0 + e1;
            rsum[mb * 2 + 1] += e2 + e3;
            csum0[nb] += e0 + e2;
            csum1[nb] += e1 + e3;
            *(__half2*)(tile + lrA * TPAD + lc)       = __floats2half2_rn(e0 * e0, e1 * e1);
            *(__half2*)(tile + (lrA + 8) * TPAD + lc) = __floats2half2_rn(e2 * e2, e3 * e3);
            if (vA && vc)
                *(float2*)(mconf + ((size_t)b * LDIM + glA) * LDIM + gc) = make_float2(0.f, 0.f);
            if (vB && vc)
                *(float2*)(mconf + ((size_t)b * LDIM + glB) * LDIM + gc) = make_float2(0.f, 0.f);
        }
    }
    __syncthreads();

    // coalesced e2 flush: 128 rows x 128 cols half = 2048 uint4, 8 per thread
#pragma unroll
    for (int i = 0; i < 8; i++) {
        int idx = tid + 256 * i;
        int row = idx >> 4, u = idx & 15;
        int gr = l0 + row, gc = s0 + u * 8;
        if (gr < LDIM && gc < LDIM) {
            uint4 v = *(uint4*)(tile + row * TPAD + u * 8);
            *(uint4*)(g_e2 + ((size_t)b * LDIM + gr) * LDIM + gc) = v;
        }
    }

#pragma unroll
    for (int h = 0; h < 4; h++) {
        rsum[h] += __shfl_xor_sync(0xFFFFFFFFu, rsum[h], 1);
        rsum[h] += __shfl_xor_sync(0xFFFFFFFFu, rsum[h], 2);
    }
#pragma unroll
    for (int nb = 0; nb < 8; nb++) {
#pragma unroll
        for (int o = 4; o <= 16; o <<= 1) {
            csum0[nb] += __shfl_xor_sync(0xFFFFFFFFu, csum0[nb], o);
            csum1[nb] += __shfl_xor_sync(0xFFFFFFFFu, csum1[nb], o);
        }
    }
    __syncthreads();     // tile fully flushed; safe to reuse smem for rs/cs

    float* rs = (float*)smc;
    float* cs = (float*)(smc + 1024);
    if ((lane & 3) == 0) {
#pragma unroll
        for (int h = 0; h < 4; h++) {
            int rl = wm * 32 + (h >> 1) * 16 + (h & 1) * 8 + (lane >> 2);
            rs[wn * 128 + rl] = rsum[h];
        }
    }
    if (lane < 4) {
#pragma unroll
        for (int nb = 0; nb < 8; nb++) {
            int cl = wn * 64 + nb * 8 + 2 * lane;
            cs[wm * 128 + cl]     = csum0[nb];
            cs[wm * 128 + cl + 1] = csum1[nb];
        }
    }
    __syncthreads();
    if (tid < 128) {
        float rv = rs[tid] + rs[128 + tid];
        if (l0 + tid < LDIM)
            g_rowpart[((size_t)b * LDIM + l0 + tid) * NT + nt] = rv;
        float cv = cs[tid] + cs[128 + tid] + cs[256 + tid] + cs[384 + tid];
        if (s0 + tid < LDIM)
            g_colpart[((size_t)b * NT + mt) * LDIM + s0 + tid] = cv;
    }
}

// ---------------- Pass 1b: fixed-order reduce; reset max values ----------------
__global__ void k_reduce()
{
    int t = blockIdx.x * blockDim.x + threadIdx.x;
    const int n = BATCH * LDIM;
    if (t < n) {
        float s = 0.f;
#pragma unroll
        for (int i = 0; i < NT; i++) s += g_rowpart[(size_t)t * NT + i];
        g_invR[t]    = 1.f / s;
        g_rowmaxv[t] = 0u;
    } else if (t < 2 * n) {
        int u = t - n;
        int b = u / LDIM, sidx = u % LDIM;
        float s = 0.f;
#pragma unroll
        for (int i = 0; i < NT; i++) s += g_colpart[((size_t)b * NT + i) * LDIM + sidx];
        g_invC[u]    = 1.f / s;
        g_colmaxv[u] = 0u;
    }
}

// ---------------- Pass 2: conf = e2*invR*invC from fp16 scratch ----------------
__global__ __launch_bounds__(256)
void k_conf(float* __restrict__ conf)
{
    const int b  = blockIdx.z;
    const int l0 = blockIdx.y * CROWS;
    const int s0 = blockIdx.x * CCOLS;
    const int t  = threadIdx.x, warp = t >> 5, lane = t & 31;
    const int j0 = s0 + 4 * t;
    const bool jok = j0 < LDIM;

    __shared__ float sInvR[CROWS];
    __shared__ float wr[8][CROWS];

    if (t < CROWS) sInvR[t] = g_invR[b * LDIM + l0 + t];
    __syncthreads();

    const float4 invc = jok ? *(const float4*)(g_invC + b * LDIM + j0)
                            : make_float4(0.f, 0.f, 0.f, 0.f);

    float4 cv = make_float4(0.f, 0.f, 0.f, 0.f);
    size_t base = ((size_t)b * LDIM + l0) * LDIM + (jok ? j0 : 0);

#pragma unroll 2
    for (int r = 0; r < CROWS; r++, base += LDIM) {
        float rm = 0.f;
        if (jok) {
            uint2 raw = *(const uint2*)(g_e2 + base);
            float2 f01 = __half22float2(*(__half2*)&raw.x);
            float2 f23 = __half22float2(*(__half2*)&raw.y);
            const float tR = sInvR[r];
            float4 cf;
            cf.x = f01.x * (tR * invc.x);
            cf.y = f01.y * (tR * invc.y);
            cf.z = f23.x * (tR * invc.z);
            cf.w = f23.y * (tR * invc.w);
            *(float4*)(conf + base) = cf;

            cv.x = fmaxf(cv.x, cf.x);
            cv.y = fmaxf(cv.y, cf.y);
            cv.z = fmaxf(cv.z, cf.z);
            cv.w = fmaxf(cv.w, cf.w);
            rm = fmaxf(fmaxf(cf.x, cf.y), fmaxf(cf.z, cf.w));
        }
#pragma unroll
        for (int o = 16; o > 0; o >>= 1)
            rm = fmaxf(rm, __shfl_xor_sync(0xFFFFFFFFu, rm, o));
        if (lane == 0) wr[warp][r] = rm;
    }

    if (jok) {
        atomicMax(&g_colmaxv[b * LDIM + j0 + 0], __float_as_uint(cv.x));
        atomicMax(&g_colmaxv[b * LDIM + j0 + 1], __float_as_uint(cv.y));
        atomicMax(&g_colmaxv[b * LDIM + j0 + 2], __float_as_uint(cv.z));
        atomicMax(&g_colmaxv[b * LDIM + j0 + 3], __float_as_uint(cv.w));
    }
    __syncthreads();
    if (t < CROWS) {
        float m = wr[0][t];
#pragma unroll
        for (int w = 1; w < 8; w++) m = fmaxf(m, wr[w][t]);
        atomicMax(&g_rowmaxv[b * LDIM + l0 + t], __float_as_uint(m));
    }
}

// ---------------- Pass 2b: flag = any(rowmax > THR) ----------------------------
__global__ void k_flag()
{
    __shared__ int any;
    if (threadIdx.x == 0) any = 0;
    __syncthreads();
    int loc = 0;
    for (int i = threadIdx.x; i < BATCH * LDIM; i += 256)
        if (__uint_as_float(g_rowmaxv[i]) > THRV) loc = 1;
    if (loc) any = 1;
    __syncthreads();
    if (threadIdx.x == 0) g_flag = any;
}

// ---------------- Pass 3: equality-based mutual-NN recovery (early-exit) -------
__global__ __launch_bounds__(256)
void k_recover(const float* __restrict__ conf, float* __restrict__ mconf)
{
    if (g_flag == 0) return;
    const int b  = blockIdx.z;
    const int l0 = blockIdx.y * CROWS;
    const int s0 = blockIdx.x * CCOLS;
    const int t  = threadIdx.x;
    const int j0 = s0 + 4 * t;
    const bool jok = j0 < LDIM;

    __shared__ float srm[CROWS];
    __shared__ int bany;
    if (t == 0) bany = 0;
    __syncthreads();
    if (t < CROWS) {
        float v = __uint_as_float(g_rowmaxv[b * LDIM + l0 + t]);
        srm[t] = v;
        if (v > THRV) bany = 1;
    }
    __syncthreads();
    if (!bany || !jok) return;

    float4 cm;
    cm.x = __uint_as_float(g_colmaxv[b * LDIM + j0 + 0]);
    cm.y = __uint_as_float(g_colmaxv[b * LDIM + j0 + 1]);
    cm.z = __uint_as_float(g_colmaxv[b * LDIM + j0 + 2]);
    cm.w = __uint_as_float(g_colmaxv[b * LDIM + j0 + 3]);
    const bool bj0 = border_ok(j0), bj1 = border_ok(j0 + 1),
               bj2 = border_ok(j0 + 2), bj3 = border_ok(j0 + 3);

    size_t base = ((size_t)b * LDIM + l0) * LDIM + j0;
    for (int r = 0; r < CROWS; r++, base += LDIM) {
        const float rm = srm[r];
        if (rm > THRV && border_ok(l0 + r)) {
            float4 cf = *(const float4*)(conf + base);
            if (cf.x > THRV && cf.x == rm && cf.x == cm.x && bj0) mconf[base + 0] = cf.x;
            if (cf.y > THRV && cf.y == rm && cf.y == cm.y && bj1) mconf[base + 1] = cf.y;
            if (cf.z > THRV && cf.z == rm && cf.z == cm.z && bj2) mconf[base + 2] = cf.z;
            if (cf.w > THRV && cf.w == rm && cf.w == cm.w && bj3) mconf[base + 3] = cf.w;
        }
    }
}

// ---------------- launch -------------------------------------------------------
extern "C" void kernel_launch(void* const* d_in, const int* in_sizes, int n_in,
                              void* d_out, int out_size)
{
    const float *f0 = nullptr, *f1 = nullptr, *temp = nullptr;
    for (int i = 0; i < n_in; i++) {
        if (in_sizes[i] == 1) { if (!temp) temp = (const float*)d_in[i]; }
        else { if (!f0) f0 = (const float*)d_in[i]; else if (!f1) f1 = (const float*)d_in[i]; }
    }

    float* conf  = (float*)d_out;
    float* mconf = conf + (size_t)out_size / 2;

    cudaFuncSetAttribute(k_gemm_hmma, cudaFuncAttributeMaxDynamicSharedMemorySize, SMEM_BYTES);

    const int NSPLIT = 2 * BATCH * LDIM * CDIM / 8;
    k_split<<<(NSPLIT + 255) / 256, 256>>>(f0, f1);

    dim3 g1(NT, NT, BATCH);
    k_gemm_hmma<<<g1, 256, SMEM_BYTES>>>(temp, mconf);

    const int n2 = 2 * BATCH * LDIM;
    k_reduce<<<(n2 + 255) / 256, 256>>>();

    dim3 g2((LDIM + CCOLS - 1) / CCOLS, LDIM / CROWS, BATCH);
    k_conf<<<g2, 256>>>(conf);

    k_flag<<<1, 256>>>();
    k_recover<<<g2, 256>>>(conf, mconf);
}

// round 16
// speedup vs baseline: 1.1615x; 1.0379x over previous
#include <cuda_runtime.h>
#include <cuda_fp16.h>
#include <cstdint>

#define LDIM   4800
#define CDIM   256
#define BATCH  2
#define BM     128
#define BN     128
#define BK     64
#define NT     38          // ceil(4800/128)
#define THRV   0.2f
#define CCOLS  1024        // k_conf cols per block (4 per thread)
#define CROWS  64          // k_conf rows per block
#define TPAD   136         // e2 smem tile row stride in halfs

// ---------------- static device scratch (no allocations) ----------------------
__device__ __half g_h0[BATCH * LDIM * CDIM];
__device__ __half g_h1[BATCH * LDIM * CDIM];
__device__ __half g_e2[(size_t)BATCH * LDIM * LDIM];   // staged e^2, fp16 (92 MB)
__device__ float        g_rowpart[BATCH * LDIM * NT];
__device__ float        g_colpart[BATCH * NT * LDIM];
__device__ float        g_invR[BATCH * LDIM];
__device__ float        g_invC[BATCH * LDIM];
__device__ unsigned int g_rowmaxv[BATCH * LDIM];
__device__ unsigned int g_colmaxv[BATCH * LDIM];
__device__ int          g_flag;

// ---------------- helpers ------------------------------------------------------
static __device__ __forceinline__ uint32_t smem_u32(const void* p) {
    uint32_t a;
    asm("{ .reg .u64 t; cvta.to.shared.u64 t, %1; cvt.u32.u64 %0, t; }" : "=r"(a) : "l"(p));
    return a;
}
#define CP16(saddr, gptr) \
    asm volatile("cp.async.cg.shared.global [%0], [%1], 16;" :: "r"(saddr), "l"(gptr) : "memory")
#define CP_COMMIT() asm volatile("cp.async.commit_group;" ::: "memory")
#define CP_WAIT(n)  asm volatile("cp.async.wait_group %0;" :: "n"(n) : "memory")

static __device__ __forceinline__ void ldsm4(uint32_t* f, uint32_t addr) {
    asm volatile("ldmatrix.sync.aligned.m8n8.x4.shared.b16 {%0,%1,%2,%3}, [%4];"
                 : "=r"(f[0]), "=r"(f[1]), "=r"(f[2]), "=r"(f[3]) : "r"(addr));
}
static __device__ __forceinline__ void mma16816(float* d, const uint32_t* a,
                                                uint32_t b0, uint32_t b1) {
    asm volatile("mma.sync.aligned.m16n8k16.row.col.f32.f16.f16.f32 "
                 "{%0,%1,%2,%3}, {%4,%5,%6,%7}, {%8,%9}, {%0,%1,%2,%3};"
                 : "+f"(d[0]), "+f"(d[1]), "+f"(d[2]), "+f"(d[3])
                 : "r"(a[0]), "r"(a[1]), "r"(a[2]), "r"(a[3]), "r"(b0), "r"(b1));
}
// fast exp2: FFMA-only. rel err ~2e-6.
static __device__ __forceinline__ float fexp2(float y) {
    float m = y + 12582912.f;
    float r = y - (m - 12582912.f);
    float p =               1.3333558e-3f;
    p = fmaf(p, r,          9.6181291e-3f);
    p = fmaf(p, r,          5.5504109e-2f);
    p = fmaf(p, r,          2.4022651e-1f);
    p = fmaf(p, r,          6.9314718e-1f);
    p = fmaf(p, r,          1.0f);
    return __uint_as_float(__float_as_uint(p) + (__float_as_uint(m) << 23));
}
__device__ __forceinline__ bool border_ok(int idx) {
    int h = idx / 80, w = idx % 80;
    return (h >= 2) && (h < 58) && (w >= 2) && (w < 78);
}

// smem: 3 stages x (A 16KB + B 16KB). 2 CTAs/SM x 96KB = 192KB <= 228KB.
// Epilogue reuses [0, 34816) as the e2 half tile [128][TPAD].
#define SMEM_BYTES 98304

// ---------------- Pass 0: fp32 -> fp16 -----------------------------------------
__global__ void k_split(const float* __restrict__ f0, const float* __restrict__ f1) {
    const int NH = BATCH * LDIM * CDIM / 8;
    int t = blockIdx.x * blockDim.x + threadIdx.x;
    if (t >= 2 * NH) return;
    int half = (t >= NH);
    size_t off = (size_t)(half ? t - NH : t) * 8;
    const float4* s = (const float4*)((half ? f1 : f0) + off);
    float4 a = s[0], b = s[1];
    float x[8] = {a.x, a.y, a.z, a.w, b.x, b.y, b.z, b.w};
    uint32_t hw[4];
#pragma unroll
    for (int i = 0; i < 4; i++) {
        __half2 h = __floats2half2_rn(x[2 * i], x[2 * i + 1]);
        hw[i] = *(uint32_t*)&h;
    }
    *(uint4*)((half ? g_h1 : g_h0) + off) = make_uint4(hw[0], hw[1], hw[2], hw[3]);
}

// ---------------- Pass 1: HMMA GEMM (fp16), coalesced e^2 via smem -------------
__global__ __launch_bounds__(256, 2)
void k_gemm_hmma(const float* __restrict__ tempp, float* __restrict__ mconf)
{
    extern __shared__ char smc[];
    const uint32_t sbase = smem_u32(smc);
    const uint32_t sA[3] = {sbase,         sbase + 16384, sbase + 32768};
    const uint32_t sB[3] = {sbase + 49152, sbase + 65536, sbase + 81920};

    const int b  = blockIdx.z;
    const int mt = blockIdx.y;
    const int nt = blockIdx.x;
    const int l0 = mt * BM;
    const int s0 = nt * BN;
    const int tid  = threadIdx.x;
    const int lane = tid & 31;
    const int wid  = tid >> 5;
    const int wm   = wid & 3;
    const int wn   = wid >> 2;
    const size_t bb = (size_t)b * LDIM * CDIM;

    float acc[2][8][4];
#pragma unroll
    for (int i = 0; i < 2; i++)
#pragma unroll
        for (int j = 0; j < 8; j++)
#pragma unroll
            for (int q = 0; q < 4; q++) acc[i][j][q] = 0.f;

    auto issue = [&](int c) {
        const int st = c % 3;
        const __half* A = g_h0 + bb + c * BK;
        const __half* B = g_h1 + bb + c * BK;
#pragma unroll
        for (int i = 0; i < 4; i++) {
            int v = tid + 256 * i;
            int r = v >> 3, u = v & 7;
            uint32_t off = (uint32_t)(r * 128 + ((u ^ (r & 7)) << 4));
            int ga = l0 + r; if (ga >= LDIM) ga = 0;
            CP16(sA[st] + off, (const char*)(A + (size_t)ga * CDIM + u * 8));
            int gbr = s0 + r; if (gbr >= LDIM) gbr = 0;
            CP16(sB[st] + off, (const char*)(B + (size_t)gbr * CDIM + u * 8));
        }
    };

    issue(0); CP_COMMIT();
    issue(1); CP_COMMIT();

    for (int c = 0; c < 4; c++) {
        if (c < 3) CP_WAIT(1); else CP_WAIT(0);
        __syncthreads();

        const int st = c % 3;
#pragma unroll
        for (int ks = 0; ks < 4; ks++) {
            uint32_t af[2][4], bf[4][4];
            const uint32_t cu = (uint32_t)((ks * 2 + (lane >> 4)) << 4);
#pragma unroll
            for (int mb = 0; mb < 2; mb++) {
                int row = wm * 32 + mb * 16 + (lane & 15);
                uint32_t off = (uint32_t)(row * 128) + (cu ^ (uint32_t)((row & 7) << 4));
                ldsm4(af[mb], sA[st] + off);
            }
#pragma unroll
            for (int ng = 0; ng < 4; ng++) {
                int row = wn * 64 + ng * 16 + (lane & 15);
                uint32_t off = (uint32_t)(row * 128) + (cu ^ (uint32_t)((row & 7) << 4));
                ldsm4(bf[ng], sB[st] + off);
            }
#pragma unroll
            for (int mb = 0; mb < 2; mb++)
#pragma unroll
                for (int nb = 0; nb < 8; nb++)
                    mma16816(acc[mb][nb], af[mb], bf[nb >> 1][nb & 1], bf[nb >> 1][(nb & 1) + 2]);
        }

        if (c < 2) { issue(c + 2); CP_COMMIT(); }
    }
    __syncthreads();

    // ---- epilogue: e = 2^(sim*scale); sums fp32; e^2 -> smem tile; mconf 0 ----
    const float scale = tempp[0] * (1.4426950408889634f / 256.0f);
    const int lrow = wm * 32 + (lane >> 2);
    const int lcol = wn * 64 + 2 * (lane & 3);
    __half* tile = (__half*)smc;                      // [128][TPAD] halfs

    float rsum[4] = {0.f, 0.f, 0.f, 0.f};
    float csum0[8], csum1[8];
#pragma unroll
    for (int nb = 0; nb < 8; nb++) { csum0[nb] = 0.f; csum1[nb] = 0.f; }

#pragma unroll
    for (int mb = 0; mb < 2; mb++) {
        const int lrA = lrow + mb * 16;
        const int glA = l0 + lrA;
        const int glB = glA + 8;
        const bool vA = glA < LDIM, vB = glB < LDIM;
#pragma unroll
        for (int nb = 0; nb < 8; nb++) {
            const int lc = lcol + nb * 8;
            const int gc = s0 + lc;
            const bool vc = gc < LDIM;
            float e0 = fexp2(acc[mb][nb][0] * scale);
            float e1 = fexp2(acc[mb][nb][1] * scale);
            float e2 = fexp2(acc[mb][nb][2] * scale);
            float e3 = fexp2(acc[mb][nb][3] * scale);
            if (!(vA && vc)) { e0 = 0.f; e1 = 0.f; }
            if (!(vB && vc)) { e2 = 0.f; e3 = 0.f; }
            rsum[mb * 2 + 0] += e0 + e1;
            rsum[mb * 2 + 1] += e2 + e3;
            csum0[nb] += e0 + e2;
            csum1[nb] += e1 + e3;
            *(__half2*)(tile + lrA * TPAD + lc)       = __floats2half2_rn(e0 * e0, e1 * e1);
            *(__half2*)(tile + (lrA + 8) * TPAD + lc) = __floats2half2_rn(e2 * e2, e3 * e3);
            if (vA && vc)
                *(float2*)(mconf + ((size_t)b * LDIM + glA) * LDIM + gc) = make_float2(0.f, 0.f);
            if (vB && vc)
                *(float2*)(mconf + ((size_t)b * LDIM + glB) * LDIM + gc) = make_float2(0.f, 0.f);
        }
    }
    __syncthreads();

    // coalesced e2 flush: 128 rows x 128 cols half = 2048 uint4, 8 per thread
#pragma unroll
    for (int i = 0; i < 8; i++) {
        int idx = tid + 256 * i;
        int row = idx >> 4, u = idx & 15;
        int gr = l0 + row, gc = s0 + u * 8;
        if (gr < LDIM && gc < LDIM) {
            uint4 v = *(uint4*)(tile + row * TPAD + u * 8);
            *(uint4*)(g_e2 + ((size_t)b * LDIM + gr) * LDIM + gc) = v;
        }
    }

#pragma unroll
    for (int h = 0; h < 4; h++) {
        rsum[h] += __shfl_xor_sync(0xFFFFFFFFu, rsum[h], 1);
        rsum[h] += __shfl_xor_sync(0xFFFFFFFFu, rsum[h], 2);
    }
#pragma unroll
    for (int nb = 0; nb < 8; nb++) {
#pragma unroll
        for (int o = 4; o <= 16; o <<= 1) {
            csum0[nb] += __shfl_xor_sync(0xFFFFFFFFu, csum0[nb], o);
            csum1[nb] += __shfl_xor_sync(0xFFFFFFFFu, csum1[nb], o);
        }
    }
    __syncthreads();     // tile fully flushed; safe to reuse smem for rs/cs

    float* rs = (float*)smc;
    float* cs = (float*)(smc + 1024);
    if ((lane & 3) == 0) {
#pragma unroll
        for (int h = 0; h < 4; h++) {
            int rl = wm * 32 + (h >> 1) * 16 + (h & 1) * 8 + (lane >> 2);
            rs[wn * 128 + rl] = rsum[h];
        }
    }
    if (lane < 4) {
#pragma unroll
        for (int nb = 0; nb < 8; nb++) {
            int cl = wn * 64 + nb * 8 + 2 * lane;
            cs[wm * 128 + cl]     = csum0[nb];
            cs[wm * 128 + cl + 1] = csum1[nb];
        }
    }
    __syncthreads();
    if (tid < 128) {
        float rv = rs[tid] + rs[128 + tid];
        if (l0 + tid < LDIM)
            g_rowpart[((size_t)b * LDIM + l0 + tid) * NT + nt] = rv;
        float cv = cs[tid] + cs[128 + tid] + cs[256 + tid] + cs[384 + tid];
        if (s0 + tid < LDIM)
            g_colpart[((size_t)b * NT + mt) * LDIM + s0 + tid] = cv;
    }
}

// ---------------- Pass 1b: fixed-order reduce; reset max values + flag ---------
__global__ void k_reduce()
{
    int t = blockIdx.x * blockDim.x + threadIdx.x;
    if (t == 0) g_flag = 0;
    const int n = BATCH * LDIM;
    if (t < n) {
        float s = 0.f;
#pragma unroll
        for (int i = 0; i < NT; i++) s += g_rowpart[(size_t)t * NT + i];
        g_invR[t]    = 1.f / s;
        g_rowmaxv[t] = 0u;
    } else if (t < 2 * n) {
        int u = t - n;
        int b = u / LDIM, sidx = u % LDIM;
        float s = 0.f;
#pragma unroll
        for (int i = 0; i < NT; i++) s += g_colpart[((size_t)b * NT + i) * LDIM + sidx];
        g_invC[u]    = 1.f / s;
        g_colmaxv[u] = 0u;
    }
}

// ---------------- Pass 2: conf = e2*invR*invC; fused threshold flag -------------
__global__ __launch_bounds__(256)
void k_conf(float* __restrict__ conf)
{
    const int b  = blockIdx.z;
    const int l0 = blockIdx.y * CROWS;
    const int s0 = blockIdx.x * CCOLS;
    const int t  = threadIdx.x, warp = t >> 5, lane = t & 31;
    const int j0 = s0 + 4 * t;
    const bool jok = j0 < LDIM;

    __shared__ float sInvR[CROWS];
    __shared__ float wr[8][CROWS];

    if (t < CROWS) sInvR[t] = g_invR[b * LDIM + l0 + t];
    __syncthreads();

    const float4 invc = jok ? *(const float4*)(g_invC + b * LDIM + j0)
                            : make_float4(0.f, 0.f, 0.f, 0.f);

    float4 cv = make_float4(0.f, 0.f, 0.f, 0.f);
    size_t base = ((size_t)b * LDIM + l0) * LDIM + (jok ? j0 : 0);

#pragma unroll 2
    for (int r = 0; r < CROWS; r++, base += LDIM) {
        float rm = 0.f;
        if (jok) {
            uint2 raw = *(const uint2*)(g_e2 + base);
            float2 f01 = __half22float2(*(__half2*)&raw.x);
            float2 f23 = __half22float2(*(__half2*)&raw.y);
            const float tR = sInvR[r];
            float4 cf;
            cf.x = f01.x * (tR * invc.x);
            cf.y = f01.y * (tR * invc.y);
            cf.z = f23.x * (tR * invc.z);
            cf.w = f23.y * (tR * invc.w);
            *(float4*)(conf + base) = cf;

            cv.x = fmaxf(cv.x, cf.x);
            cv.y = fmaxf(cv.y, cf.y);
            cv.z = fmaxf(cv.z, cf.z);
            cv.w = fmaxf(cv.w, cf.w);
            rm = fmaxf(fmaxf(cf.x, cf.y), fmaxf(cf.z, cf.w));
        }
#pragma unroll
        for (int o = 16; o > 0; o >>= 1)
            rm = fmaxf(rm, __shfl_xor_sync(0xFFFFFFFFu, rm, o));
        if (lane == 0) wr[warp][r] = rm;
    }

    if (jok) {
        atomicMax(&g_colmaxv[b * LDIM + j0 + 0], __float_as_uint(cv.x));
        atomicMax(&g_colmaxv[b * LDIM + j0 + 1], __float_as_uint(cv.y));
        atomicMax(&g_colmaxv[b * LDIM + j0 + 2], __float_as_uint(cv.z));
        atomicMax(&g_colmaxv[b * LDIM + j0 + 3], __float_as_uint(cv.w));
    }
    __syncthreads();
    if (t < CROWS) {
        float m = wr[0][t];
#pragma unroll
        for (int w = 1; w < 8; w++) m = fmaxf(m, wr[w][t]);
        atomicMax(&g_rowmaxv[b * LDIM + l0 + t], __float_as_uint(m));
        if (m > THRV) g_flag = 1;        // benign same-value race; replaces k_flag
    }
}

// ---------------- Pass 3: equality-based mutual-NN recovery (early-exit) -------
__global__ __launch_bounds__(256)
void k_recover(const float* __restrict__ conf, float* __restrict__ mconf)
{
    if (g_flag == 0) return;
    const int b  = blockIdx.z;
    const int l0 = blockIdx.y * CROWS;
    const int s0 = blockIdx.x * CCOLS;
    const int t  = threadIdx.x;
    const int j0 = s0 + 4 * t;
    const bool jok = j0 < LDIM;

    __shared__ float srm[CROWS];
    __shared__ int bany;
    if (t == 0) bany = 0;
    __syncthreads();
    if (t < CROWS) {
        float v = __uint_as_float(g_rowmaxv[b * LDIM + l0 + t]);
        srm[t] = v;
        if (v > THRV) bany = 1;
    }
    __syncthreads();
    if (!bany || !jok) return;

    float4 cm;
    cm.x = __uint_as_float(g_colmaxv[b * LDIM + j0 + 0]);
    cm.y = __uint_as_float(g_colmaxv[b * LDIM + j0 + 1]);
    cm.z = __uint_as_float(g_colmaxv[b * LDIM + j0 + 2]);
    cm.w = __uint_as_float(g_colmaxv[b * LDIM + j0 + 3]);
    const bool bj0 = border_ok(j0), bj1 = border_ok(j0 + 1),
               bj2 = border_ok(j0 + 2), bj3 = border_ok(j0 + 3);

    size_t base = ((size_t)b * LDIM + l0) * LDIM + j0;
    for (int r = 0; r < CROWS; r++, base += LDIM) {
        const float rm = srm[r];
        if (rm > THRV && border_ok(l0 + r)) {
            float4 cf = *(const float4*)(conf + base);
            if (cf.x > THRV && cf.x == rm && cf.x == cm.x && bj0) mconf[base + 0] = cf.x;
            if (cf.y > THRV && cf.y == rm && cf.y == cm.y && bj1) mconf[base + 1] = cf.y;
            if (cf.z > THRV && cf.z == rm && cf.z == cm.z && bj2) mconf[base + 2] = cf.z;
            if (cf.w > THRV && cf.w == rm && cf.w == cm.w && bj3) mconf[base + 3] = cf.w;
        }
    }
}

// ---------------- launch -------------------------------------------------------
extern "C" void kernel_launch(void* const* d_in, const int* in_sizes, int n_in,
                              void* d_out, int out_size)
{
    const float *f0 = nullptr, *f1 = nullptr, *temp = nullptr;
    for (int i = 0; i < n_in; i++) {
        if (in_sizes[i] == 1) { if (!temp) temp = (const float*)d_in[i]; }
        else { if (!f0) f0 = (const float*)d_in[i]; else if (!f1) f1 = (const float*)d_in[i]; }
    }

    float* conf  = (float*)d_out;
    float* mconf = conf + (size_t)out_size / 2;

    cudaFuncSetAttribute(k_gemm_hmma, cudaFuncAttributeMaxDynamicSharedMemorySize, SMEM_BYTES);

    const int NSPLIT = 2 * BATCH * LDIM * CDIM / 8;
    k_split<<<(NSPLIT + 255) / 256, 256>>>(f0, f1);

    dim3 g1(NT, NT, BATCH);
    k_gemm_hmma<<<g1, 256, SMEM_BYTES>>>(temp, mconf);

    const int n2 = 2 * BATCH * LDIM;
    k_reduce<<<(n2 + 255) / 256, 256>>>();

    dim3 g2((LDIM + CCOLS - 1) / CCOLS, LDIM / CROWS, BATCH);
    k_conf<<<g2, 256>>>(conf);

    k_recover<<<g2, 256>>>(conf, mconf);
}

// round 17
// speedup vs baseline: 1.1691x; 1.0065x over previous
#include <cuda_runtime.h>
#include <cuda_fp16.h>
#include <cstdint>

#define LDIM   4800
#define CDIM   256
#define BATCH  2
#define BM     128
#define BN     128
#define BK     64
#define NT     38          // ceil(4800/128)
#define THRV   0.2f
#define CCOLS  1024        // k_conf cols per block (4 per thread)
#define CROWS  64          // k_conf rows per block
#define TPAD   136         // e2 smem tile row stride in halfs

// ---------------- static device scratch (no allocations) ----------------------
__device__ __half g_h0[BATCH * LDIM * CDIM];
__device__ __half g_h1[BATCH * LDIM * CDIM];
__device__ __half g_e2[(size_t)BATCH * LDIM * LDIM];   // staged e^2, fp16 (92 MB)
__device__ float        g_rowpart[BATCH * LDIM * NT];
__device__ float        g_colpart[BATCH * NT * LDIM];
__device__ float        g_invR[BATCH * LDIM];
__device__ float        g_invC[BATCH * LDIM];
__device__ unsigned int g_rowmaxv[BATCH * LDIM];
__device__ unsigned int g_colmaxv[BATCH * LDIM];
__device__ int          g_flag;

// ---------------- helpers ------------------------------------------------------
static __device__ __forceinline__ uint32_t smem_u32(const void* p) {
    uint32_t a;
    asm("{ .reg .u64 t; cvta.to.shared.u64 t, %1; cvt.u32.u64 %0, t; }" : "=r"(a) : "l"(p));
    return a;
}
#define CP16(saddr, gptr) \
    asm volatile("cp.async.cg.shared.global [%0], [%1], 16;" :: "r"(saddr), "l"(gptr) : "memory")
#define CP_COMMIT() asm volatile("cp.async.commit_group;" ::: "memory")
#define CP_WAIT(n)  asm volatile("cp.async.wait_group %0;" :: "n"(n) : "memory")

static __device__ __forceinline__ void ldsm4(uint32_t* f, uint32_t addr) {
    asm volatile("ldmatrix.sync.aligned.m8n8.x4.shared.b16 {%0,%1,%2,%3}, [%4];"
                 : "=r"(f[0]), "=r"(f[1]), "=r"(f[2]), "=r"(f[3]) : "r"(addr));
}
static __device__ __forceinline__ void mma16816(float* d, const uint32_t* a,
                                                uint32_t b0, uint32_t b1) {
    asm volatile("mma.sync.aligned.m16n8k16.row.col.f32.f16.f16.f32 "
                 "{%0,%1,%2,%3}, {%4,%5,%6,%7}, {%8,%9}, {%0,%1,%2,%3};"
                 : "+f"(d[0]), "+f"(d[1]), "+f"(d[2]), "+f"(d[3])
                 : "r"(a[0]), "r"(a[1]), "r"(a[2]), "r"(a[3]), "r"(b0), "r"(b1));
}
// fast exp2: FFMA-only. rel err ~2e-6.
static __device__ __forceinline__ float fexp2(float y) {
    float m = y + 12582912.f;
    float r = y - (m - 12582912.f);
    float p =               1.3333558e-3f;
    p = fmaf(p, r,          9.6181291e-3f);
    p = fmaf(p, r,          5.5504109e-2f);
    p = fmaf(p, r,          2.4022651e-1f);
    p = fmaf(p, r,          6.9314718e-1f);
    p = fmaf(p, r,          1.0f);
    return __uint_as_float(__float_as_uint(p) + (__float_as_uint(m) << 23));
}
__device__ __forceinline__ bool border_ok(int idx) {
    int h = idx / 80, w = idx % 80;
    return (h >= 2) && (h < 58) && (w >= 2) && (w < 78);
}

// smem: 3 stages x (A 16KB + B 16KB). 2 CTAs/SM x 96KB = 192KB <= 228KB.
// Epilogue reuses [0, 34816) as the e2 half tile [128][TPAD].
#define SMEM_BYTES 98304

// ---------------- Pass 0: fp32 -> fp16 -----------------------------------------
__global__ void k_split(const float* __restrict__ f0, const float* __restrict__ f1) {
    const int NH = BATCH * LDIM * CDIM / 8;
    int t = blockIdx.x * blockDim.x + threadIdx.x;
    if (t >= 2 * NH) return;
    int half = (t >= NH);
    size_t off = (size_t)(half ? t - NH : t) * 8;
    const float4* s = (const float4*)((half ? f1 : f0) + off);
    float4 a = __ldcs(s), b = __ldcs(s + 1);
    float x[8] = {a.x, a.y, a.z, a.w, b.x, b.y, b.z, b.w};
    uint32_t hw[4];
#pragma unroll
    for (int i = 0; i < 4; i++) {
        __half2 h = __floats2half2_rn(x[2 * i], x[2 * i + 1]);
        hw[i] = *(uint32_t*)&h;
    }
    *(uint4*)((half ? g_h1 : g_h0) + off) = make_uint4(hw[0], hw[1], hw[2], hw[3]);
}

// ---------------- Pass 1: HMMA GEMM (fp16), coalesced e^2 via smem -------------
__global__ __launch_bounds__(256, 2)
void k_gemm_hmma(const float* __restrict__ tempp, float* __restrict__ mconf)
{
    extern __shared__ char smc[];
    const uint32_t sbase = smem_u32(smc);
    const uint32_t sA[3] = {sbase,         sbase + 16384, sbase + 32768};
    const uint32_t sB[3] = {sbase + 49152, sbase + 65536, sbase + 81920};

    const int b  = blockIdx.z;
    const int mt = blockIdx.y;
    const int nt = blockIdx.x;
    const int l0 = mt * BM;
    const int s0 = nt * BN;
    const int tid  = threadIdx.x;
    const int lane = tid & 31;
    const int wid  = tid >> 5;
    const int wm   = wid & 3;
    const int wn   = wid >> 2;
    const size_t bb = (size_t)b * LDIM * CDIM;

    float acc[2][8][4];
#pragma unroll
    for (int i = 0; i < 2; i++)
#pragma unroll
        for (int j = 0; j < 8; j++)
#pragma unroll
            for (int q = 0; q < 4; q++) acc[i][j][q] = 0.f;

    auto issue = [&](int c) {
        const int st = c % 3;
        const __half* A = g_h0 + bb + c * BK;
        const __half* B = g_h1 + bb + c * BK;
#pragma unroll
        for (int i = 0; i < 4; i++) {
            int v = tid + 256 * i;
            int r = v >> 3, u = v & 7;
            uint32_t off = (uint32_t)(r * 128 + ((u ^ (r & 7)) << 4));
            int ga = l0 + r; if (ga >= LDIM) ga = 0;
            CP16(sA[st] + off, (const char*)(A + (size_t)ga * CDIM + u * 8));
            int gbr = s0 + r; if (gbr >= LDIM) gbr = 0;
            CP16(sB[st] + off, (const char*)(B + (size_t)gbr * CDIM + u * 8));
        }
    };

    issue(0); CP_COMMIT();
    issue(1); CP_COMMIT();

    for (int c = 0; c < 4; c++) {
        if (c < 3) CP_WAIT(1); else CP_WAIT(0);
        __syncthreads();

        const int st = c % 3;
#pragma unroll
        for (int ks = 0; ks < 4; ks++) {
            uint32_t af[2][4], bf[4][4];
            const uint32_t cu = (uint32_t)((ks * 2 + (lane >> 4)) << 4);
#pragma unroll
            for (int mb = 0; mb < 2; mb++) {
                int row = wm * 32 + mb * 16 + (lane & 15);
                uint32_t off = (uint32_t)(row * 128) + (cu ^ (uint32_t)((row & 7) << 4));
                ldsm4(af[mb], sA[st] + off);
            }
#pragma unroll
            for (int ng = 0; ng < 4; ng++) {
                int row = wn * 64 + ng * 16 + (lane & 15);
                uint32_t off = (uint32_t)(row * 128) + (cu ^ (uint32_t)((row & 7) << 4));
                ldsm4(bf[ng], sB[st] + off);
            }
#pragma unroll
            for (int mb = 0; mb < 2; mb++)
#pragma unroll
                for (int nb = 0; nb < 8; nb++)
                    mma16816(acc[mb][nb], af[mb], bf[nb >> 1][nb & 1], bf[nb >> 1][(nb & 1) + 2]);
        }

        if (c < 2) { issue(c + 2); CP_COMMIT(); }
    }
    __syncthreads();

    // ---- epilogue: e = 2^(sim*scale); sums fp32; e^2 -> smem tile; mconf 0 ----
    const float scale = tempp[0] * (1.4426950408889634f / 256.0f);
    const int lrow = wm * 32 + (lane >> 2);
    const int lcol = wn * 64 + 2 * (lane & 3);
    __half* tile = (__half*)smc;                      // [128][TPAD] halfs

    float rsum[4] = {0.f, 0.f, 0.f, 0.f};
    float csum0[8], csum1[8];
#pragma unroll
    for (int nb = 0; nb < 8; nb++) { csum0[nb] = 0.f; csum1[nb] = 0.f; }

#pragma unroll
    for (int mb = 0; mb < 2; mb++) {
        const int lrA = lrow + mb * 16;
        const int glA = l0 + lrA;
        const int glB = glA + 8;
        const bool vA = glA < LDIM, vB = glB < LDIM;
#pragma unroll
        for (int nb = 0; nb < 8; nb++) {
            const int lc = lcol + nb * 8;
            const int gc = s0 + lc;
            const bool vc = gc < LDIM;
            float e0 = fexp2(acc[mb][nb][0] * scale);
            float e1 = fexp2(acc[mb][nb][1] * scale);
            float e2 = fexp2(acc[mb][nb][2] * scale);
            float e3 = fexp2(acc[mb][nb][3] * scale);
            if (!(vA && vc)) { e0 = 0.f; e1 = 0.f; }
            if (!(vB && vc)) { e2 = 0.f; e3 = 0.f; }
            rsum[mb * 2 + 0] += e0 + e1;
            rsum[mb * 2 + 1] += e2 + e3;
            csum0[nb] += e0 + e2;
            csum1[nb] += e1 + e3;
            *(__half2*)(tile + lrA * TPAD + lc)       = __floats2half2_rn(e0 * e0, e1 * e1);
            *(__half2*)(tile + (lrA + 8) * TPAD + lc) = __floats2half2_rn(e2 * e2, e3 * e3);
            if (vA && vc)
                __stcs((float2*)(mconf + ((size_t)b * LDIM + glA) * LDIM + gc), make_float2(0.f, 0.f));
            if (vB && vc)
                __stcs((float2*)(mconf + ((size_t)b * LDIM + glB) * LDIM + gc), make_float2(0.f, 0.f));
        }
    }
    __syncthreads();

    // coalesced e2 flush: 128 rows x 128 cols half = 2048 uint4, 8 per thread
#pragma unroll
    for (int i = 0; i < 8; i++) {
        int idx = tid + 256 * i;
        int row = idx >> 4, u = idx & 15;
        int gr = l0 + row, gc = s0 + u * 8;
        if (gr < LDIM && gc < LDIM) {
            uint4 v = *(uint4*)(tile + row * TPAD + u * 8);
            __stcs((uint4*)(g_e2 + ((size_t)b * LDIM + gr) * LDIM + gc), v);
        }
    }

#pragma unroll
    for (int h = 0; h < 4; h++) {
        rsum[h] += __shfl_xor_sync(0xFFFFFFFFu, rsum[h], 1);
        rsum[h] += __shfl_xor_sync(0xFFFFFFFFu, rsum[h], 2);
    }
#pragma unroll
    for (int nb = 0; nb < 8; nb++) {
#pragma unroll
        for (int o = 4; o <= 16; o <<= 1) {
            csum0[nb] += __shfl_xor_sync(0xFFFFFFFFu, csum0[nb], o);
            csum1[nb] += __shfl_xor_sync(0xFFFFFFFFu, csum1[nb], o);
        }
    }
    __syncthreads();     // tile fully flushed; safe to reuse smem for rs/cs

    float* rs = (float*)smc;
    float* cs = (float*)(smc + 1024);
    if ((lane & 3) == 0) {
#pragma unroll
        for (int h = 0; h < 4; h++) {
            int rl = wm * 32 + (h >> 1) * 16 + (h & 1) * 8 + (lane >> 2);
            rs[wn * 128 + rl] = rsum[h];
        }
    }
    if (lane < 4) {
#pragma unroll
        for (int nb = 0; nb < 8; nb++) {
            int cl = wn * 64 + nb * 8 + 2 * lane;
            cs[wm * 128 + cl]     = csum0[nb];
            cs[wm * 128 + cl + 1] = csum1[nb];
        }
    }
    __syncthreads();
    if (tid < 128) {
        float rv = rs[tid] + rs[128 + tid];
        if (l0 + tid < LDIM)
            g_rowpart[((size_t)b * LDIM + l0 + tid) * NT + nt] = rv;
        float cv = cs[tid] + cs[128 + tid] + cs[256 + tid] + cs[384 + tid];
        if (s0 + tid < LDIM)
            g_colpart[((size_t)b * NT + mt) * LDIM + s0 + tid] = cv;
    }
}

// ---------------- Pass 1b: fixed-order reduce; reset max values + flag ---------
__global__ void k_reduce()
{
    int t = blockIdx.x * blockDim.x + threadIdx.x;
    if (t == 0) g_flag = 0;
    const int n = BATCH * LDIM;
    if (t < n) {
        float s = 0.f;
#pragma unroll
        for (int i = 0; i < NT; i++) s += g_rowpart[(size_t)t * NT + i];
        g_invR[t]    = 1.f / s;
        g_rowmaxv[t] = 0u;
    } else if (t < 2 * n) {
        int u = t - n;
        int b = u / LDIM, sidx = u % LDIM;
        float s = 0.f;
#pragma unroll
        for (int i = 0; i < NT; i++) s += g_colpart[((size_t)b * NT + i) * LDIM + sidx];
        g_invC[u]    = 1.f / s;
        g_colmaxv[u] = 0u;
    }
}

// ---------------- Pass 2: conf = e2*invR*invC; fused threshold flag -------------
__global__ __launch_bounds__(256)
void k_conf(float* __restrict__ conf)
{
    const int b  = blockIdx.z;
    const int l0 = blockIdx.y * CROWS;
    const int s0 = blockIdx.x * CCOLS;
    const int t  = threadIdx.x, warp = t >> 5, lane = t & 31;
    const int j0 = s0 + 4 * t;
    const bool jok = j0 < LDIM;

    __shared__ float sInvR[CROWS];
    __shared__ float wr[8][CROWS];

    if (t < CROWS) sInvR[t] = g_invR[b * LDIM + l0 + t];
    __syncthreads();

    const float4 invc = jok ? *(const float4*)(g_invC + b * LDIM + j0)
                            : make_float4(0.f, 0.f, 0.f, 0.f);

    float4 cv = make_float4(0.f, 0.f, 0.f, 0.f);
    size_t base = ((size_t)b * LDIM + l0) * LDIM + (jok ? j0 : 0);

#pragma unroll 2
    for (int r = 0; r < CROWS; r++, base += LDIM) {
        float rm = 0.f;
        if (jok) {
            uint2 raw = __ldcs((const uint2*)(g_e2 + base));
            float2 f01 = __half22float2(*(__half2*)&raw.x);
            float2 f23 = __half22float2(*(__half2*)&raw.y);
            const float tR = sInvR[r];
            float4 cf;
            cf.x = f01.x * (tR * invc.x);
            cf.y = f01.y * (tR * invc.y);
            cf.z = f23.x * (tR * invc.z);
            cf.w = f23.y * (tR * invc.w);
            __stcs((float4*)(conf + base), cf);

            cv.x = fmaxf(cv.x, cf.x);
            cv.y = fmaxf(cv.y, cf.y);
            cv.z = fmaxf(cv.z, cf.z);
            cv.w = fmaxf(cv.w, cf.w);
            rm = fmaxf(fmaxf(cf.x, cf.y), fmaxf(cf.z, cf.w));
        }
#pragma unroll
        for (int o = 16; o > 0; o >>= 1)
            rm = fmaxf(rm, __shfl_xor_sync(0xFFFFFFFFu, rm, o));
        if (lane == 0) wr[warp][r] = rm;
    }

    if (jok) {
        atomicMax(&g_colmaxv[b * LDIM + j0 + 0], __float_as_uint(cv.x));
        atomicMax(&g_colmaxv[b * LDIM + j0 + 1], __float_as_uint(cv.y));
        atomicMax(&g_colmaxv[b * LDIM + j0 + 2], __float_as_uint(cv.z));
        atomicMax(&g_colmaxv[b * LDIM + j0 + 3], __float_as_uint(cv.w));
    }
    __syncthreads();
    if (t < CROWS) {
        float m = wr[0][t];
#pragma unroll
        for (int w = 1; w < 8; w++) m = fmaxf(m, wr[w][t]);
        atomicMax(&g_rowmaxv[b * LDIM + l0 + t], __float_as_uint(m));
        if (m > THRV) g_flag = 1;        // benign same-value race
    }
}

// ---------------- Pass 3: equality-based mutual-NN recovery (early-exit) -------
__global__ __launch_bounds__(256)
void k_recover(const float* __restrict__ conf, float* __restrict__ mconf)
{
    if (g_flag == 0) return;
    const int b  = blockIdx.z;
    const int l0 = blockIdx.y * CROWS;
    const int s0 = blockIdx.x * CCOLS;
    const int t  = threadIdx.x;
    const int j0 = s0 + 4 * t;
    const bool jok = j0 < LDIM;

    __shared__ float srm[CROWS];
    __shared__ int bany;
    if (t == 0) bany = 0;
    __syncthreads();
    if (t < CROWS) {
        float v = __uint_as_float(g_rowmaxv[b * LDIM + l0 + t]);
        srm[t] = v;
        if (v > THRV) bany = 1;
    }
    __syncthreads();
    if (!bany || !jok) return;

    float4 cm;
    cm.x = __uint_as_float(g_colmaxv[b * LDIM + j0 + 0]);
    cm.y = __uint_as_float(g_colmaxv[b * LDIM + j0 + 1]);
    cm.z = __uint_as_float(g_colmaxv[b * LDIM + j0 + 2]);
    cm.w = __uint_as_float(g_colmaxv[b * LDIM + j0 + 3]);
    const bool bj0 = border_ok(j0), bj1 = border_ok(j0 + 1),
               bj2 = border_ok(j0 + 2), bj3 = border_ok(j0 + 3);

    size_t base = ((size_t)b * LDIM + l0) * LDIM + j0;
    for (int r = 0; r < CROWS; r++, base += LDIM) {
        const float rm = srm[r];
        if (rm > THRV && border_ok(l0 + r)) {
            float4 cf = __ldcs((const float4*)(conf + base));
            if (cf.x > THRV && cf.x == rm && cf.x == cm.x && bj0) mconf[base + 0] = cf.x;
            if (cf.y > THRV && cf.y == rm && cf.y == cm.y && bj1) mconf[base + 1] = cf.y;
            if (cf.z > THRV && cf.z == rm && cf.z == cm.z && bj2) mconf[base + 2] = cf.z;
            if (cf.w > THRV && cf.w == rm && cf.w == cm.w && bj3) mconf[base + 3] = cf.w;
        }
    }
}

// ---------------- launch -------------------------------------------------------
extern "C" void kernel_launch(void* const* d_in, const int* in_sizes, int n_in,
                              void* d_out, int out_size)
{
    const float *f0 = nullptr, *f1 = nullptr, *temp = nullptr;
    for (int i = 0; i < n_in; i++) {
        if (in_sizes[i] == 1) { if (!temp) temp = (const float*)d_in[i]; }
        else { if (!f0) f0 = (const float*)d_in[i]; else if (!f1) f1 = (const float*)d_in[i]; }
    }

    float* conf  = (float*)d_out;
    float* mconf = conf + (size_t)out_size / 2;

    cudaFuncSetAttribute(k_gemm_hmma, cudaFuncAttributeMaxDynamicSharedMemorySize, SMEM_BYTES);

    const int NSPLIT = 2 * BATCH * LDIM * CDIM / 8;
    k_split<<<(NSPLIT + 255) / 256, 256>>>(f0, f1);

    dim3 g1(NT, NT, BATCH);
    k_gemm_hmma<<<g1, 256, SMEM_BYTES>>>(temp, mconf);

    const int n2 = 2 * BATCH * LDIM;
    k_reduce<<<(n2 + 255) / 256, 256>>>();

    dim3 g2((LDIM + CCOLS - 1) / CCOLS, LDIM / CROWS, BATCH);
    k_conf<<<g2, 256>>>(conf);

    k_recover<<<g2, 256>>>(conf, mconf);
}